// round 2
// baseline (speedup 1.0000x reference)
#include <cuda_runtime.h>
#include <math.h>

#define B_  8
#define L_  4096
#define D_  512
#define H_  8
#define CH  64
#define O3  1536   // 3 * H_ * CH

// Scratch (allocation-free rule: __device__ globals)
__device__ float g_qkv[(size_t)B_ * O3 * L_];          // [B][3*512][L]  ~201 MB
__device__ float g_ctxp[64 * 32 * 64 * 64];            // [bh][split][d][e] ~33.5 MB
__device__ float g_M[(size_t)B_ * D_ * D_];            // [B][dout][c]   8 MB

// ---------------------------------------------------------------------------
// Kernel 1: qkv[b,o,l] = sum_d Wqkv[o,d] * x[b,l,d]
// 128x128x16 tile, 256 threads, 8x8 per thread.
// ---------------------------------------------------------------------------
__global__ __launch_bounds__(256, 2)
void k_gemm_qkv(const float* __restrict__ x, const float* __restrict__ W) {
    const int b  = blockIdx.z;
    const int m0 = blockIdx.y * 128;   // o
    const int n0 = blockIdx.x * 128;   // l
    const float* A  = W;                                // [1536,512]
    const float* Bx = x + (size_t)b * L_ * D_;          // [4096,512]
    float* Cp = g_qkv + (size_t)b * O3 * L_;

    __shared__ __align__(16) float As[16][132];
    __shared__ __align__(16) float Bs[16][132];

    const int tid = threadIdx.x;
    const int tx = tid & 15, ty = tid >> 4;

    float acc[8][8];
#pragma unroll
    for (int i = 0; i < 8; i++)
#pragma unroll
        for (int j = 0; j < 8; j++) acc[i][j] = 0.f;

    for (int k0 = 0; k0 < D_; k0 += 16) {
#pragma unroll
        for (int i = 0; i < 2; i++) {
            int idx = tid * 2 + i;          // 0..511 float4s
            int row = idx >> 2;             // 0..127
            int kk  = (idx & 3) << 2;       // 0,4,8,12
            float4 v = *(const float4*)(A + (size_t)(m0 + row) * D_ + k0 + kk);
            As[kk + 0][row] = v.x; As[kk + 1][row] = v.y;
            As[kk + 2][row] = v.z; As[kk + 3][row] = v.w;
            float4 w = *(const float4*)(Bx + (size_t)(n0 + row) * D_ + k0 + kk);
            Bs[kk + 0][row] = w.x; Bs[kk + 1][row] = w.y;
            Bs[kk + 2][row] = w.z; Bs[kk + 3][row] = w.w;
        }
        __syncthreads();
#pragma unroll
        for (int kk = 0; kk < 16; kk++) {
            float ar[8], br[8];
            float4 a0 = *(const float4*)&As[kk][ty * 8];
            float4 a1 = *(const float4*)&As[kk][ty * 8 + 4];
            float4 b0 = *(const float4*)&Bs[kk][tx * 8];
            float4 b1 = *(const float4*)&Bs[kk][tx * 8 + 4];
            ar[0]=a0.x; ar[1]=a0.y; ar[2]=a0.z; ar[3]=a0.w;
            ar[4]=a1.x; ar[5]=a1.y; ar[6]=a1.z; ar[7]=a1.w;
            br[0]=b0.x; br[1]=b0.y; br[2]=b0.z; br[3]=b0.w;
            br[4]=b1.x; br[5]=b1.y; br[6]=b1.z; br[7]=b1.w;
#pragma unroll
            for (int i = 0; i < 8; i++)
#pragma unroll
                for (int j = 0; j < 8; j++) acc[i][j] = fmaf(ar[i], br[j], acc[i][j]);
        }
        __syncthreads();
    }
#pragma unroll
    for (int i = 0; i < 8; i++) {
        float* crow = Cp + (size_t)(m0 + ty * 8 + i) * L_ + n0 + tx * 8;
        *(float4*)(crow + 0) = make_float4(acc[i][0], acc[i][1], acc[i][2], acc[i][3]);
        *(float4*)(crow + 4) = make_float4(acc[i][4], acc[i][5], acc[i][6], acc[i][7]);
    }
}

// ---------------------------------------------------------------------------
// Kernel 2: softmax over L for each k-row (B*512 rows of length 4096)
// ---------------------------------------------------------------------------
__global__ __launch_bounds__(256)
void k_softmax_rows() {
    const int r = blockIdx.x;           // 0..511
    const int b = blockIdx.y;
    float* row = g_qkv + ((size_t)b * O3 + D_ + r) * L_;
    __shared__ float red[256];
    const int tid = threadIdx.x;

    float m = -3.0e38f;
    for (int i = tid; i < L_; i += 256) m = fmaxf(m, row[i]);
    red[tid] = m; __syncthreads();
    for (int s = 128; s > 0; s >>= 1) {
        if (tid < s) red[tid] = fmaxf(red[tid], red[tid + s]);
        __syncthreads();
    }
    m = red[0]; __syncthreads();

    float sum = 0.f;
    for (int i = tid; i < L_; i += 256) sum += expf(row[i] - m);
    red[tid] = sum; __syncthreads();
    for (int s = 128; s > 0; s >>= 1) {
        if (tid < s) red[tid] += red[tid + s];
        __syncthreads();
    }
    const float inv = 1.0f / red[0];

    for (int i = tid; i < L_; i += 256) row[i] = expf(row[i] - m) * inv;
}

// ---------------------------------------------------------------------------
// Kernel 3: softmax over C (64) for q, per (b,h,l)
// ---------------------------------------------------------------------------
__global__ __launch_bounds__(256)
void k_softmax_q() {
    const int l = blockIdx.x * 256 + threadIdx.x;
    const int h = blockIdx.y;
    const int b = blockIdx.z;
    float* base = g_qkv + ((size_t)b * O3 + h * CH) * L_ + l;

    float m = -3.0e38f;
#pragma unroll
    for (int c = 0; c < CH; c++) m = fmaxf(m, base[(size_t)c * L_]);
    float s = 0.f;
#pragma unroll
    for (int c = 0; c < CH; c++) s += expf(base[(size_t)c * L_] - m);
    const float inv = 1.0f / s;
#pragma unroll
    for (int c = 0; c < CH; c++) base[(size_t)c * L_] = expf(base[(size_t)c * L_] - m) * inv;
}

// ---------------------------------------------------------------------------
// Kernel 4: split-K context partials: ctx[b,h,d,e] = sum_n k[d,n]*v[e,n]
// grid (64 bh, 32 splits), 64 threads, 8x8 per thread.
// ---------------------------------------------------------------------------
__global__ __launch_bounds__(64)
void k_ctx() {
    const int bh = blockIdx.x;
    const int sp = blockIdx.y;
    const int b = bh >> 3, h = bh & 7;
    const float* kbase = g_qkv + ((size_t)b * O3 + D_ + h * CH) * L_;
    const float* vbase = g_qkv + ((size_t)b * O3 + 2 * D_ + h * CH) * L_;

    __shared__ float ks[64][65];
    __shared__ float vs[64][65];
    const int tid = threadIdx.x;
    const int tx = tid & 7, ty = tid >> 3;

    float acc[8][8];
#pragma unroll
    for (int i = 0; i < 8; i++)
#pragma unroll
        for (int j = 0; j < 8; j++) acc[i][j] = 0.f;

    for (int n0 = sp * 128; n0 < sp * 128 + 128; n0 += 64) {
#pragma unroll
        for (int i = 0; i < 16; i++) {
            int idx = i * 64 + tid;         // 0..1023 float4s
            int row = idx >> 4;
            int col = (idx & 15) << 2;
            float4 kv = *(const float4*)(kbase + (size_t)row * L_ + n0 + col);
            ks[row][col+0]=kv.x; ks[row][col+1]=kv.y; ks[row][col+2]=kv.z; ks[row][col+3]=kv.w;
            float4 vv = *(const float4*)(vbase + (size_t)row * L_ + n0 + col);
            vs[row][col+0]=vv.x; vs[row][col+1]=vv.y; vs[row][col+2]=vv.z; vs[row][col+3]=vv.w;
        }
        __syncthreads();
#pragma unroll 8
        for (int nn = 0; nn < 64; nn++) {
            float kr[8], vr[8];
#pragma unroll
            for (int i = 0; i < 8; i++) kr[i] = ks[ty * 8 + i][nn];
#pragma unroll
            for (int j = 0; j < 8; j++) vr[j] = vs[tx * 8 + j][nn];
#pragma unroll
            for (int i = 0; i < 8; i++)
#pragma unroll
                for (int j = 0; j < 8; j++) acc[i][j] = fmaf(kr[i], vr[j], acc[i][j]);
        }
        __syncthreads();
    }
    float* out = g_ctxp + (size_t)(bh * 32 + sp) * 4096;
#pragma unroll
    for (int i = 0; i < 8; i++)
#pragma unroll
        for (int j = 0; j < 8; j++)
            out[(size_t)(ty * 8 + i) * 64 + tx * 8 + j] = acc[i][j];
}

// ---------------------------------------------------------------------------
// Kernel 5: reduce ctx partials + build M_b[dout, h*64+d] = sum_e Wout[dout,h*64+e]*ctx[d,e]
// one block per (b,h), 256 threads.
// ---------------------------------------------------------------------------
__global__ __launch_bounds__(256)
void k_M(const float* __restrict__ Wout) {
    const int bh = blockIdx.x;
    const int b = bh >> 3, h = bh & 7;
    __shared__ float ctxs[64][65];
    const int tid = threadIdx.x;

    for (int e0 = tid; e0 < 4096; e0 += 256) {
        float sum = 0.f;
        const float* p = g_ctxp + (size_t)bh * 32 * 4096 + e0;
#pragma unroll
        for (int s = 0; s < 32; s++) sum += p[(size_t)s * 4096];
        ctxs[e0 >> 6][e0 & 63] = sum;
    }
    __syncthreads();

    const int d  = tid & 63;
    const int dq = tid >> 6;   // 0..3
    float* Mb = g_M + (size_t)b * D_ * D_;
    for (int dout = dq; dout < D_; dout += 4) {
        const float* wrow = Wout + (size_t)dout * D_ + h * CH;
        float sum = 0.f;
#pragma unroll
        for (int e = 0; e < CH; e++) sum = fmaf(__ldg(wrow + e), ctxs[d][e], sum);
        Mb[(size_t)dout * D_ + h * CH + d] = sum;
    }
}

// ---------------------------------------------------------------------------
// Kernel 6: y[b,l,dout] = sum_c M_b[dout,c] * q[b,c,l] + bout[dout]
// 128(l) x 128(dout) x 16 tile.
// ---------------------------------------------------------------------------
__global__ __launch_bounds__(256, 2)
void k_gemm_out(const float* __restrict__ bout, float* __restrict__ y) {
    const int b  = blockIdx.z;
    const int l0 = blockIdx.y * 128;
    const int n0 = blockIdx.x * 128;   // dout
    const float* Q  = g_qkv + (size_t)b * O3 * L_;   // [512 rows c][L]
    const float* Mb = g_M + (size_t)b * D_ * D_;     // [512 dout][512 c]
    float* Y = y + (size_t)b * L_ * D_;

    __shared__ __align__(16) float As[16][132];      // [k][l]
    __shared__ __align__(16) float Bs[16][132];      // [k][dout]

    const int tid = threadIdx.x;
    const int tx = tid & 15, ty = tid >> 4;

    float acc[8][8];
#pragma unroll
    for (int i = 0; i < 8; i++)
#pragma unroll
        for (int j = 0; j < 8; j++) acc[i][j] = 0.f;

    for (int k0 = 0; k0 < D_; k0 += 16) {
#pragma unroll
        for (int i = 0; i < 2; i++) {
            int idx = tid * 2 + i;          // 0..511 float4s
            // As: Q[k0+kk][l0 + 0..127] — contiguous along l
            int kk  = idx >> 5;             // 0..15
            int col = (idx & 31) << 2;      // 0..124
            float4 v = *(const float4*)(Q + (size_t)(k0 + kk) * L_ + l0 + col);
            *(float4*)&As[kk][col] = v;
            // Bs: Mb rows n0..n0+127, 16 contiguous c — transpose into [k][n]
            int row = idx >> 2;
            int k2  = (idx & 3) << 2;
            float4 w = *(const float4*)(Mb + (size_t)(n0 + row) * D_ + k0 + k2);
            Bs[k2 + 0][row] = w.x; Bs[k2 + 1][row] = w.y;
            Bs[k2 + 2][row] = w.z; Bs[k2 + 3][row] = w.w;
        }
        __syncthreads();
#pragma unroll
        for (int kk = 0; kk < 16; kk++) {
            float ar[8], br[8];
            float4 a0 = *(const float4*)&As[kk][ty * 8];
            float4 a1 = *(const float4*)&As[kk][ty * 8 + 4];
            float4 b0 = *(const float4*)&Bs[kk][tx * 8];
            float4 b1 = *(const float4*)&Bs[kk][tx * 8 + 4];
            ar[0]=a0.x; ar[1]=a0.y; ar[2]=a0.z; ar[3]=a0.w;
            ar[4]=a1.x; ar[5]=a1.y; ar[6]=a1.z; ar[7]=a1.w;
            br[0]=b0.x; br[1]=b0.y; br[2]=b0.z; br[3]=b0.w;
            br[4]=b1.x; br[5]=b1.y; br[6]=b1.z; br[7]=b1.w;
#pragma unroll
            for (int i = 0; i < 8; i++)
#pragma unroll
                for (int j = 0; j < 8; j++) acc[i][j] = fmaf(ar[i], br[j], acc[i][j]);
        }
        __syncthreads();
    }

    float bo[8];
#pragma unroll
    for (int j = 0; j < 8; j++) bo[j] = __ldg(bout + n0 + tx * 8 + j);
#pragma unroll
    for (int i = 0; i < 8; i++) {
        float* yrow = Y + (size_t)(l0 + ty * 8 + i) * D_ + n0 + tx * 8;
        *(float4*)(yrow + 0) = make_float4(acc[i][0]+bo[0], acc[i][1]+bo[1], acc[i][2]+bo[2], acc[i][3]+bo[3]);
        *(float4*)(yrow + 4) = make_float4(acc[i][4]+bo[4], acc[i][5]+bo[5], acc[i][6]+bo[6], acc[i][7]+bo[7]);
    }
}

// ---------------------------------------------------------------------------
extern "C" void kernel_launch(void* const* d_in, const int* in_sizes, int n_in,
                              void* d_out, int out_size) {
    const float* x    = (const float*)d_in[0];
    const float* Wqkv = (const float*)d_in[1];
    const float* Wout = (const float*)d_in[2];
    const float* bout = (const float*)d_in[3];
    float* y = (float*)d_out;

    k_gemm_qkv<<<dim3(L_ / 128, O3 / 128, B_), 256>>>(x, Wqkv);
    k_softmax_rows<<<dim3(D_, B_), 256>>>();
    k_softmax_q<<<dim3(L_ / 256, H_, B_), 256>>>();
    k_ctx<<<dim3(64, 32), 64>>>();
    k_M<<<64, 256>>>(Wout);
    k_gemm_out<<<dim3(D_ / 128, L_ / 128, B_), 256>>>(bout, y);
}

// round 5
// speedup vs baseline: 1.8449x; 1.8449x over previous
#include <cuda_runtime.h>
#include <cuda_bf16.h>
#include <cstdint>
#include <math.h>

#define B_  8
#define L_  4096
#define D_  512
#define H_  8
#define CH  64
#define O3  1536

// ---------------- scratch (__device__ globals; no allocs allowed) ----------
__device__ float g_kv[(size_t)B_ * 1024 * L_];                 // k rows 0..511, v rows 512..1023, [b][row][L]
__device__ float g_qT[(size_t)B_ * L_ * D_];                   // q pre-softmax, [b][l][c]
__device__ float g_ctxp[64 * 32 * 64 * 64];                    // [bh][split][d][e]
__device__ __nv_bfloat16 g_xhi[(size_t)B_ * L_ * D_], g_xlo[(size_t)B_ * L_ * D_];
__device__ __nv_bfloat16 g_Whi[(size_t)O3 * D_],      g_Wlo[(size_t)O3 * D_];
__device__ __nv_bfloat16 g_qhi[(size_t)B_ * L_ * D_], g_qlo[(size_t)B_ * L_ * D_];
__device__ __nv_bfloat16 g_Mhi[(size_t)B_ * D_ * D_], g_Mlo[(size_t)B_ * D_ * D_];

// ---------------- PTX helpers ---------------------------------------------
__device__ __forceinline__ uint32_t smem_u32(const void* p) {
    uint32_t a;
    asm("{ .reg .u64 t; cvta.to.shared.u64 t, %1; cvt.u32.u64 %0, t; }" : "=r"(a) : "l"(p));
    return a;
}
#define SWZ128(b) ((b) ^ (((b) >> 3) & 0x70))

__device__ __forceinline__ void cp16(uint32_t dst, const void* src) {
    asm volatile("cp.async.cg.shared.global [%0], [%1], 16;" :: "r"(dst), "l"(src));
}
#define CP_COMMIT() asm volatile("cp.async.commit_group;")

__device__ __forceinline__ void ldsm_x4(uint32_t r[4], uint32_t a) {
    asm volatile("ldmatrix.sync.aligned.m8n8.x4.shared.b16 {%0,%1,%2,%3}, [%4];"
                 : "=r"(r[0]), "=r"(r[1]), "=r"(r[2]), "=r"(r[3]) : "r"(a));
}
__device__ __forceinline__ void ldsm_x2(uint32_t r[2], uint32_t a) {
    asm volatile("ldmatrix.sync.aligned.m8n8.x2.shared.b16 {%0,%1}, [%2];"
                 : "=r"(r[0]), "=r"(r[1]) : "r"(a));
}
__device__ __forceinline__ void mma_bf16(float d[4], const uint32_t a[4], const uint32_t b[2]) {
    asm volatile("mma.sync.aligned.m16n8k16.row.col.f32.bf16.bf16.f32 "
                 "{%0,%1,%2,%3}, {%4,%5,%6,%7}, {%8,%9}, {%0,%1,%2,%3};"
                 : "+f"(d[0]), "+f"(d[1]), "+f"(d[2]), "+f"(d[3])
                 : "r"(a[0]), "r"(a[1]), "r"(a[2]), "r"(a[3]), "r"(b[0]), "r"(b[1]));
}

// ---------------- Kernel: fp32 -> bf16 hi/lo split -------------------------
__global__ __launch_bounds__(256)
void k_split(const float* __restrict__ src, int which, int n4) {
    int i = blockIdx.x * 256 + threadIdx.x;
    if (i >= n4) return;
    __nv_bfloat16* hi = which ? g_Whi : g_xhi;
    __nv_bfloat16* lo = which ? g_Wlo : g_xlo;
    float4 v = ((const float4*)src)[i];
    __nv_bfloat16 h0 = __float2bfloat16(v.x), h1 = __float2bfloat16(v.y);
    __nv_bfloat16 h2 = __float2bfloat16(v.z), h3 = __float2bfloat16(v.w);
    __nv_bfloat16 l0 = __float2bfloat16(v.x - __bfloat162float(h0));
    __nv_bfloat16 l1 = __float2bfloat16(v.y - __bfloat162float(h1));
    __nv_bfloat16 l2 = __float2bfloat16(v.z - __bfloat162float(h2));
    __nv_bfloat16 l3 = __float2bfloat16(v.w - __bfloat162float(h3));
    ((__nv_bfloat162*)hi)[i * 2 + 0] = __nv_bfloat162(h0, h1);
    ((__nv_bfloat162*)hi)[i * 2 + 1] = __nv_bfloat162(h2, h3);
    ((__nv_bfloat162*)lo)[i * 2 + 0] = __nv_bfloat162(l0, l1);
    ((__nv_bfloat162*)lo)[i * 2 + 1] = __nv_bfloat162(l2, l3);
}

// ---------------- mma.sync bf16-split GEMM ---------------------------------
// D[m,n] = sum_k A[m,k]*B[n,k], hi/lo 3-pass.  CTA 128x128, 8 warps (2m x 4n),
// K-chunk 32, 2-stage cp.async.  Smem rows: 128B = hi k0..31 | lo k0..31.
// mode 0: qkv (A=W, B=x; m0<512 -> q transposed to g_qT, else -> g_kv rows)
// mode 1: out (A=q, B=M; D+bias -> y)
#define STAGE_B  32768
#define SMEM_MM  (2 * STAGE_B)

__global__ __launch_bounds__(256, 1)
void k_mm(float* __restrict__ Cout, const float* __restrict__ bias, int mode) {
    extern __shared__ char smem[];
    const int tid  = threadIdx.x;
    const int wid  = tid >> 5, lane = tid & 31;
    const int wm   = wid & 1;          // 0..1  (m offset wm*64)
    const int wn   = wid >> 1;         // 0..3  (n offset wn*32)
    const int b    = blockIdx.z;
    const int m0   = blockIdx.y * 128;
    const int n0   = blockIdx.x * 128;

    const uint32_t smbase = smem_u32(smem);

    const __nv_bfloat16 *Ahi, *Alo, *Bhi, *Blo;
    if (mode == 0) {
        Ahi = g_Whi + (size_t)m0 * D_;              Alo = g_Wlo + (size_t)m0 * D_;
        Bhi = g_xhi + ((size_t)b * L_ + n0) * D_;   Blo = g_xlo + ((size_t)b * L_ + n0) * D_;
    } else {
        Ahi = g_qhi + ((size_t)b * L_ + m0) * D_;   Alo = g_qlo + ((size_t)b * L_ + m0) * D_;
        Bhi = g_Mhi + ((size_t)b * D_ + n0) * D_;   Blo = g_Mlo + ((size_t)b * D_ + n0) * D_;
    }

    // stage loader: 2048 cp16 / 256 threads = 8 each
    auto load_stage = [&](int s, int d0) {
        uint32_t base = smbase + s * STAGE_B;
#pragma unroll
        for (int i = 0; i < 8; i++) {
            int id = i * 256 + tid;                // 0..2047
            int reg = id >> 10;                    // 0 = A, 1 = B
            int r   = (id >> 3) & 127;
            int u   = id & 7;                      // 0..3 hi, 4..7 lo
            const __nv_bfloat16* hp = reg ? Bhi : Ahi;
            const __nv_bfloat16* lp = reg ? Blo : Alo;
            const __nv_bfloat16* src = (u < 4)
                ? hp + (size_t)r * D_ + d0 + u * 8
                : lp + (size_t)r * D_ + d0 + (u - 4) * 8;
            cp16(base + reg * 16384 + SWZ128((uint32_t)(r * 128 + u * 16)), src);
        }
        CP_COMMIT();
    };

    float acc[4][4][4];
#pragma unroll
    for (int i = 0; i < 4; i++)
#pragma unroll
        for (int j = 0; j < 4; j++)
#pragma unroll
            for (int k = 0; k < 4; k++) acc[i][j][k] = 0.f;

    // precomputed lane address components
    const uint32_t a_row = wm * 64 + (lane & 15);
    const uint32_t a_ub  = (lane >> 4);            // 0..1
    const uint32_t b_row = wn * 32 + (lane & 7);
    const uint32_t b_ub  = (lane >> 3) & 1;

    load_stage(0, 0);

    for (int kc = 0; kc < 16; kc++) {
        int s = kc & 1;
        if (kc + 1 < 16) {
            load_stage(s ^ 1, (kc + 1) * 32);
            asm volatile("cp.async.wait_group 1;");
        } else {
            asm volatile("cp.async.wait_group 0;");
        }
        __syncthreads();

        uint32_t smA = smbase + s * STAGE_B;
        uint32_t smB = smA + 16384;
#pragma unroll
        for (int sl = 0; sl < 2; sl++) {           // k16 slices within chunk
            uint32_t ah[4][4], al[4][4], bh[4][2], bl[4][2];
#pragma unroll
            for (int mt = 0; mt < 4; mt++) {
                uint32_t row = a_row + mt * 16;
                ldsm_x4(ah[mt], smA + SWZ128(row * 128 + (sl * 2 + a_ub) * 16));
                ldsm_x4(al[mt], smA + SWZ128(row * 128 + (4 + sl * 2 + a_ub) * 16));
            }
#pragma unroll
            for (int nt = 0; nt < 4; nt++) {
                uint32_t row = b_row + nt * 8;
                ldsm_x2(bh[nt], smB + SWZ128(row * 128 + (sl * 2 + b_ub) * 16));
                ldsm_x2(bl[nt], smB + SWZ128(row * 128 + (4 + sl * 2 + b_ub) * 16));
            }
#pragma unroll
            for (int mt = 0; mt < 4; mt++)
#pragma unroll
                for (int nt = 0; nt < 4; nt++) {
                    mma_bf16(acc[mt][nt], ah[mt], bh[nt]);
                    mma_bf16(acc[mt][nt], ah[mt], bl[nt]);
                    mma_bf16(acc[mt][nt], al[mt], bh[nt]);
                }
        }
        __syncthreads();
    }

    // ---- epilogue via smem, two 64-col halves ----
    float* ep = (float*)smem;                      // [128][65]
    for (int p = 0; p < 2; p++) {
        if ((wn >> 1) == p) {
            int cb = (wn & 1) * 32;
#pragma unroll
            for (int mt = 0; mt < 4; mt++)
#pragma unroll
                for (int nt = 0; nt < 4; nt++) {
                    int row = wm * 64 + mt * 16 + (lane >> 2);
                    int col = cb + nt * 8 + (lane & 3) * 2;
                    ep[row * 65 + col]           = acc[mt][nt][0];
                    ep[row * 65 + col + 1]       = acc[mt][nt][1];
                    ep[(row + 8) * 65 + col]     = acc[mt][nt][2];
                    ep[(row + 8) * 65 + col + 1] = acc[mt][nt][3];
                }
        }
        __syncthreads();
        int c0 = p * 64;
        if (mode == 0 && m0 < 512) {
            // transposed q store: g_qT[b][l = n0+c0+c][o = m0 + mg*4 ..]
            float* dst = g_qT + (size_t)b * L_ * D_;
#pragma unroll
            for (int i = 0; i < 8; i++) {
                int id = tid + 256 * i;
                int c = id >> 5, mg = id & 31;
                float4 v;
                v.x = ep[(mg * 4 + 0) * 65 + c];
                v.y = ep[(mg * 4 + 1) * 65 + c];
                v.z = ep[(mg * 4 + 2) * 65 + c];
                v.w = ep[(mg * 4 + 3) * 65 + c];
                *(float4*)(dst + (size_t)(n0 + c0 + c) * D_ + m0 + mg * 4) = v;
            }
        } else {
            float* dst; int ldc;
            if (mode == 0) { dst = g_kv + ((size_t)b * 1024 + (m0 - 512)) * L_; ldc = L_; }
            else           { dst = Cout + ((size_t)b * L_ + m0) * D_;           ldc = D_; }
#pragma unroll
            for (int i = 0; i < 8; i++) {
                int id = tid + 256 * i;
                int m = id >> 4, g = id & 15;
                float4 v;
                v.x = ep[m * 65 + g * 4 + 0];
                v.y = ep[m * 65 + g * 4 + 1];
                v.z = ep[m * 65 + g * 4 + 2];
                v.w = ep[m * 65 + g * 4 + 3];
                if (mode == 1) {
                    v.x += __ldg(bias + n0 + c0 + g * 4 + 0);
                    v.y += __ldg(bias + n0 + c0 + g * 4 + 1);
                    v.z += __ldg(bias + n0 + c0 + g * 4 + 2);
                    v.w += __ldg(bias + n0 + c0 + g * 4 + 3);
                }
                *(float4*)(dst + (size_t)m * ldc + n0 + c0 + g * 4) = v;
            }
        }
        __syncthreads();
    }
}

// ---------------- softmax over L for k rows --------------------------------
__global__ __launch_bounds__(256)
void k_softmax_rows() {
    const int r = blockIdx.x, b = blockIdx.y;
    float* row = g_kv + ((size_t)b * 1024 + r) * L_;
    __shared__ float red[256];
    const int tid = threadIdx.x;

    float m = -3.0e38f;
    for (int i = tid; i < L_; i += 256) m = fmaxf(m, row[i]);
    red[tid] = m; __syncthreads();
    for (int s = 128; s > 0; s >>= 1) { if (tid < s) red[tid] = fmaxf(red[tid], red[tid + s]); __syncthreads(); }
    m = red[0]; __syncthreads();

    float sum = 0.f;
    for (int i = tid; i < L_; i += 256) sum += expf(row[i] - m);
    red[tid] = sum; __syncthreads();
    for (int s = 128; s > 0; s >>= 1) { if (tid < s) red[tid] += red[tid + s]; __syncthreads(); }
    const float inv = 1.0f / red[0];
    for (int i = tid; i < L_; i += 256) row[i] = expf(row[i] - m) * inv;
}

// ---------------- softmax over C for q (warp per l) + bf16 split -----------
__global__ __launch_bounds__(256)
void k_softmax_q() {
    const int b = blockIdx.y;
    const int l = blockIdx.x * 8 + (threadIdx.x >> 5);
    const int lane = threadIdx.x & 31;
    const size_t off = ((size_t)b * L_ + l) * D_;
    const float* src = g_qT + off;

#pragma unroll
    for (int h = 0; h < H_; h++) {
        float2 v = *(const float2*)(src + h * CH + lane * 2);
        float m = fmaxf(v.x, v.y);
#pragma unroll
        for (int o = 16; o; o >>= 1) m = fmaxf(m, __shfl_xor_sync(0xffffffffu, m, o));
        float e0 = expf(v.x - m), e1 = expf(v.y - m);
        float s = e0 + e1;
#pragma unroll
        for (int o = 16; o; o >>= 1) s += __shfl_xor_sync(0xffffffffu, s, o);
        float inv = 1.0f / s;
        float a = e0 * inv, c = e1 * inv;
        __nv_bfloat16 h0 = __float2bfloat16(a), h1 = __float2bfloat16(c);
        __nv_bfloat16 l0 = __float2bfloat16(a - __bfloat162float(h0));
        __nv_bfloat16 l1 = __float2bfloat16(c - __bfloat162float(h1));
        *(__nv_bfloat162*)(g_qhi + off + h * CH + lane * 2) = __nv_bfloat162(h0, h1);
        *(__nv_bfloat162*)(g_qlo + off + h * CH + lane * 2) = __nv_bfloat162(l0, l1);
    }
}

// ---------------- context partials: ctx[d,e] = sum_n k[d,n] v[e,n] ---------
__global__ __launch_bounds__(64)
void k_ctx() {
    const int bh = blockIdx.x, sp = blockIdx.y;
    const int b = bh >> 3, h = bh & 7;
    const float* kbase = g_kv + ((size_t)b * 1024 + h * CH) * L_;
    const float* vbase = g_kv + ((size_t)b * 1024 + 512 + h * CH) * L_;

    __shared__ float ks[64][65];
    __shared__ float vs[64][65];
    const int tid = threadIdx.x;
    const int tx = tid & 7, ty = tid >> 3;

    float acc[8][8];
#pragma unroll
    for (int i = 0; i < 8; i++)
#pragma unroll
        for (int j = 0; j < 8; j++) acc[i][j] = 0.f;

    for (int n0 = sp * 128; n0 < sp * 128 + 128; n0 += 64) {
#pragma unroll
        for (int i = 0; i < 16; i++) {
            int idx = i * 64 + tid;
            int row = idx >> 4, col = (idx & 15) << 2;
            float4 kv = *(const float4*)(kbase + (size_t)row * L_ + n0 + col);
            ks[row][col+0]=kv.x; ks[row][col+1]=kv.y; ks[row][col+2]=kv.z; ks[row][col+3]=kv.w;
            float4 vv = *(const float4*)(vbase + (size_t)row * L_ + n0 + col);
            vs[row][col+0]=vv.x; vs[row][col+1]=vv.y; vs[row][col+2]=vv.z; vs[row][col+3]=vv.w;
        }
        __syncthreads();
#pragma unroll 8
        for (int nn = 0; nn < 64; nn++) {
            float kr[8], vr[8];
#pragma unroll
            for (int i = 0; i < 8; i++) kr[i] = ks[ty * 8 + i][nn];
#pragma unroll
            for (int j = 0; j < 8; j++) vr[j] = vs[tx * 8 + j][nn];
#pragma unroll
            for (int i = 0; i < 8; i++)
#pragma unroll
                for (int j = 0; j < 8; j++) acc[i][j] = fmaf(kr[i], vr[j], acc[i][j]);
        }
        __syncthreads();
    }
    float* out = g_ctxp + (size_t)(bh * 32 + sp) * 4096;
#pragma unroll
    for (int i = 0; i < 8; i++)
#pragma unroll
        for (int j = 0; j < 8; j++)
            out[(size_t)(ty * 8 + i) * 64 + tx * 8 + j] = acc[i][j];
}

// ---------------- reduce ctx + M = Wout-contract, emit bf16 hi/lo ----------
__global__ __launch_bounds__(256)
void k_M(const float* __restrict__ Wout) {
    const int bh = blockIdx.x;
    const int b = bh >> 3, h = bh & 7;
    __shared__ float ctxs[64][65];
    const int tid = threadIdx.x;

    for (int e0 = tid; e0 < 4096; e0 += 256) {
        float sum = 0.f;
        const float* p = g_ctxp + (size_t)bh * 32 * 4096 + e0;
#pragma unroll
        for (int s = 0; s < 32; s++) sum += p[(size_t)s * 4096];
        ctxs[e0 >> 6][e0 & 63] = sum;
    }
    __syncthreads();

    const int d = tid & 63, dq = tid >> 6;
    for (int dout = dq; dout < D_; dout += 4) {
        const float* wrow = Wout + (size_t)dout * D_ + h * CH;
        float sum = 0.f;
#pragma unroll
        for (int e = 0; e < CH; e++) sum = fmaf(__ldg(wrow + e), ctxs[d][e], sum);
        size_t o = (size_t)b * D_ * D_ + (size_t)dout * D_ + h * CH + d;
        __nv_bfloat16 hi = __float2bfloat16(sum);
        g_Mhi[o] = hi;
        g_Mlo[o] = __float2bfloat16(sum - __bfloat162float(hi));
    }
}

// ---------------------------------------------------------------------------
extern "C" void kernel_launch(void* const* d_in, const int* in_sizes, int n_in,
                              void* d_out, int out_size) {
    const float* x    = (const float*)d_in[0];
    const float* Wqkv = (const float*)d_in[1];
    const float* Wout = (const float*)d_in[2];
    const float* bout = (const float*)d_in[3];
    float* y = (float*)d_out;

    cudaFuncSetAttribute(k_mm, cudaFuncAttributeMaxDynamicSharedMemorySize, SMEM_MM);

    int n4x = B_ * L_ * D_ / 4;
    int n4w = O3 * D_ / 4;
    k_split<<<(n4x + 255) / 256, 256>>>(x, 0, n4x);
    k_split<<<(n4w + 255) / 256, 256>>>(Wqkv, 1, n4w);

    k_mm<<<dim3(32, 12, B_), 256, SMEM_MM>>>(nullptr, nullptr, 0);    // qkv
    k_softmax_rows<<<dim3(512, B_), 256>>>();
    k_softmax_q<<<dim3(512, B_), 256>>>();
    k_ctx<<<dim3(64, 32), 64>>>();
    k_M<<<64, 256>>>(Wout);
    k_mm<<<dim3(4, 32, B_), 256, SMEM_MM>>>(y, bout, 1);              // out
}